// round 11
// baseline (speedup 1.0000x reference)
#include <cuda_runtime.h>
#include <cuda_fp16.h>

#define H_ 512
#define W_ 512
#define C_ 32
#define B_ 2
#define N_ 120000
#define HW_ (H_*W_)
#define NP_ (B_*N_)

#define TW_ 32
#define TH_ 8
#define HALO_W 34
#define HALO_H 10
#define NHALO (HALO_W*HALO_H)    // 340
#define CSTRIDE 17               // u64 per halo cell (16 data + 1 pad -> 136B)

typedef unsigned long long u64;

// ---- device scratch (no allocations allowed; zero-initialized) ----
__device__ __align__(128) float  g_Qsp[B_*HW_*C_];    // spatial Q (f32), valid cells only
__device__ __align__(128) __half g_KVsp[B_*HW_*64];   // spatial KV fp16: K[32],V[32] per cell
__device__ int    g_grid[B_*HW_];
__device__ float  g_A[3*1024];
__device__ float  g_bf[3*32];
__device__ u64    g_A2p[32*48];
__device__ u64    g_bf2[48];
__device__ float  g_posP[9*32];
__device__ u64    g_posP2[9*16];
__device__ __align__(128) __half g_kvinvh[64];        // fp16: kinv[32], vinv[32]

// ---- packed f32x2 helpers ----
__device__ __forceinline__ u64 pk2(float lo, float hi){
    u64 r; asm("mov.b64 %0, {%1, %2};" : "=l"(r) : "f"(lo), "f"(hi)); return r;
}
__device__ __forceinline__ float2 unpk2(u64 v){
    float2 f; asm("mov.b64 {%0, %1}, %2;" : "=f"(f.x), "=f"(f.y) : "l"(v)); return f;
}
__device__ __forceinline__ u64 ffma2(u64 a, u64 b, u64 c){
    u64 d; asm("fma.rn.f32x2 %0, %1, %2, %3;" : "=l"(d) : "l"(a), "l"(b), "l"(c)); return d;
}
__device__ __forceinline__ u64 mul2(u64 a, u64 b){
    u64 d; asm("mul.rn.f32x2 %0, %1, %2;" : "=l"(d) : "l"(a), "l"(b)); return d;
}
__device__ __forceinline__ float hsum2(u64 a){ float2 f = unpk2(a); return f.x + f.y; }
__device__ __forceinline__ u64 h2f2(unsigned v){
    __half2 h = *reinterpret_cast<__half2*>(&v);
    float2 f = __half22float2(h);
    return pk2(f.x, f.y);
}
__device__ __forceinline__ void spl(u64 v, unsigned& lo, unsigned& hi){
    asm("mov.b64 {%0, %1}, %2;" : "=r"(lo), "=r"(hi) : "l"(v));
}

// ---------------------------------------------------------------
// K0: block 0 = fold weights + pack; blocks 1.. = grid clear
// ---------------------------------------------------------------
__global__ void __launch_bounds__(256) k_setup(
                        const float* __restrict__ wq, const float* __restrict__ bq,
                        const float* __restrict__ wk, const float* __restrict__ bk,
                        const float* __restrict__ wv, const float* __restrict__ bv,
                        const float* __restrict__ in_w, const float* __restrict__ in_b,
                        const float* __restrict__ pos_w, const float* __restrict__ pos_b){
    int t = threadIdx.x;
    if (blockIdx.x > 0){
        g_grid[(blockIdx.x - 1)*256 + t] = -1;   // 2048 blocks * 256 = B_*HW_
        return;
    }
    // A fold: 3072 items (m,c,e)
    for (int idx = t; idx < 3072; idx += 256){
        int m = idx >> 10, rem = idx & 1023, c = rem >> 5, e = rem & 31;
        const float* Wm = (m==0) ? wq : (m==1) ? wk : wv;
        const float* iw = in_w + (m*32 + c)*32;
        float a = 0.f;
#pragma unroll 8
        for (int d = 0; d < 32; d++) a += iw[d] * Wm[d*32 + e];
        g_A[m*1024 + c*32 + e] = (m==0) ? a*0.25f : a;
    }
    if (t < 96){
        int m = t >> 5, c = t & 31;
        const float* bm = (m==0) ? bq : (m==1) ? bk : bv;
        const float* iw = in_w + (m*32 + c)*32;
        float bb = 0.f;
#pragma unroll 8
        for (int d = 0; d < 32; d++) bb += iw[d] * bm[d];
        bb += in_b[m*32 + c];
        g_bf[m*32 + c] = (m==0) ? bb*0.25f : bb;
    }
    {
        const float drf[9] = {0,-1,1,0,-1,1,0,-1,1};
        const float dcf[9] = {0,0,0,1,1,1,-1,-1,-1};
        for (int idx = t; idx < 288; idx += 256){
            int s = idx >> 5, c = idx & 31;
            const float* iw = in_w + (64 + c)*32;
            float a = 0.f;
#pragma unroll 8
            for (int d = 0; d < 32; d++){
                float pos = drf[s]*pos_w[d*2+0] + dcf[s]*pos_w[d*2+1] + pos_b[d];
                a += iw[d] * pos;
            }
            g_posP[s*32 + c] = a;
        }
    }
    if (t < 64) g_kvinvh[t] = __float2half(in_b[32 + t]);   // kinv[32], vinv[32]
    __syncthreads();
    // pair packing
    for (int idx = t; idx < 1536; idx += 256){
        int e = idx & 31, jj = idx >> 5;
        int m = jj >> 4, j = jj & 15;
        float v0 = g_A[(m*32 + 2*j    )*32 + e];
        float v1 = g_A[(m*32 + 2*j + 1)*32 + e];
        g_A2p[e*48 + jj] = pk2(v0, v1);
    }
    if (t < 48){
        int m = t >> 4, j = t & 15;
        g_bf2[t] = pk2(g_bf[m*32 + 2*j], g_bf[m*32 + 2*j + 1]);
    }
    if (t >= 64 && t < 208){
        int u = t - 64;
        int s = u >> 4, k = u & 15;
        g_posP2[u] = pk2(g_posP[s*32 + 2*k], g_posP[s*32 + 2*k + 1]);
    }
}

// ---------------------------------------------------------------
// K1: LN + fused QKV GEMM + grid fill; outputs scattered to SPATIAL canvases
// ---------------------------------------------------------------
__global__ void __launch_bounds__(256) k_qkv(const float* __restrict__ feats,
                                             const float* __restrict__ ln_w,
                                             const float* __restrict__ ln_b,
                                             const int* __restrict__ coors){
    __shared__ __align__(16) u64   shA2p[32*48];   // 12KB
    __shared__ __align__(16) float Xs[32*128];     // 16KB
    __shared__ __align__(16) u64   shBp[48];
    __shared__ int shHWq[128];                     // flat spatial index per point
    int t = threadIdx.x;
    int p0 = blockIdx.x*128;
    if (t >= 128){
        int u = t - 128;
#pragma unroll
        for (int it = 0; it < 12; it++) shA2p[u + 128*it] = g_A2p[u + 128*it];
        if (u < 48) shBp[u] = g_bf2[u];
    } else {
        int p = p0 + t;   // 1875*128 == 240000 exact
        {
            int r = __ldg(&coors[2*p]), c = __ldg(&coors[2*p+1]);
            int b = p / N_;
            int hw = b*HW_ + r*W_ + c;
            g_grid[hw] = p - b*N_;
            shHWq[t] = hw;
        }
        const float4* xin = (const float4*)(feats + (size_t)p*C_);
        float x[32];
#pragma unroll
        for (int k = 0; k < 8; k++){
            float4 v = xin[k];
            x[4*k] = v.x; x[4*k+1] = v.y; x[4*k+2] = v.z; x[4*k+3] = v.w;
        }
        float mu = 0.f;
#pragma unroll
        for (int e = 0; e < 32; e++) mu += x[e];
        mu *= (1.f/32.f);
        float var = 0.f;
#pragma unroll
        for (int e = 0; e < 32; e++){ float d = x[e]-mu; var += d*d; }
        var *= (1.f/32.f);
        float inv = rsqrtf(var + 1e-5f);
#pragma unroll
        for (int k = 0; k < 32; k++)
            Xs[k*128 + t] = (x[k]-mu)*inv*__ldg(&ln_w[k]) + __ldg(&ln_b[k]);
    }
    __syncthreads();

    int i = t >> 4, j = t & 15;
    u64 acc0[8], acc1[8], acc2[8];
    {
        u64 b0 = shBp[j], b1 = shBp[16 + j], b2 = shBp[32 + j];
#pragma unroll
        for (int p8 = 0; p8 < 8; p8++){ acc0[p8] = b0; acc1[p8] = b1; acc2[p8] = b2; }
    }
#pragma unroll 2
    for (int e = 0; e < 32; e++){
        const float4* xr = (const float4*)(Xs + e*128) + i*2;
        float4 xa = xr[0], xb = xr[1];
        u64 xd[8];
        xd[0] = pk2(xa.x, xa.x); xd[1] = pk2(xa.y, xa.y);
        xd[2] = pk2(xa.z, xa.z); xd[3] = pk2(xa.w, xa.w);
        xd[4] = pk2(xb.x, xb.x); xd[5] = pk2(xb.y, xb.y);
        xd[6] = pk2(xb.z, xb.z); xd[7] = pk2(xb.w, xb.w);
        u64 a0 = shA2p[e*48 + j];
        u64 a1 = shA2p[e*48 + 16 + j];
        u64 a2 = shA2p[e*48 + 32 + j];
#pragma unroll
        for (int p8 = 0; p8 < 8; p8++){
            acc0[p8] = ffma2(a0, xd[p8], acc0[p8]);
            acc1[p8] = ffma2(a1, xd[p8], acc1[p8]);
            acc2[p8] = ffma2(a2, xd[p8], acc2[p8]);
        }
    }
#pragma unroll
    for (int p8 = 0; p8 < 8; p8++){
        size_t row = (size_t)shHWq[8*i + p8];
        *(u64*)(g_Qsp + row*32 + 2*j) = acc0[p8];
        float2 fk = unpk2(acc1[p8]);
        float2 fv = unpk2(acc2[p8]);
        __half* kv = g_KVsp + row*64;
        *(__half2*)(kv + 2*j)      = __floats2half2_rn(fk.x, fk.y);
        *(__half2*)(kv + 32 + 2*j) = __floats2half2_rn(fv.x, fv.y);
    }
}

// ---------------------------------------------------------------
// K2: spatial-tiled fused attention + projection + direct output.
//     One block per 32x8 tile. Branch-free 9-slot loop from smem halo.
// ---------------------------------------------------------------
#define SM_HALO   0
#define SM_OS     46240                  // 340*17*8
#define SM_WT     (SM_OS + 33280)        // 32*260*4
#define SM_POS    (SM_WT + 8192)         // 1024*8
#define SM_FLAG   (SM_POS + 1152)        // 144*8
#define SM_OB     (SM_FLAG + 1360)       // 340*4 -> pad
#define SMEM_ATTN (SM_OB + 144)          // 32*4 + pad = 91,744ish

__global__ void __launch_bounds__(256) k_attn(const float* __restrict__ out_w,
                                              const float* __restrict__ out_b,
                                              float* __restrict__ out){
    extern __shared__ __align__(16) char dsm[];
    u64*   shHalo = (u64*)(dsm + SM_HALO);
    float* shOs   = (float*)(dsm + SM_OS);
    u64*   shWt2  = (u64*)(dsm + SM_WT);
    u64*   shPos2 = (u64*)(dsm + SM_POS);
    float* shFlag = (float*)(dsm + SM_FLAG);
    float* shOB   = (float*)(dsm + SM_OB);

    int t = threadIdx.x;
    int b  = blockIdx.z;
    int c0 = blockIdx.x*TW_, r0 = blockIdx.y*TH_;

    // stage constants
#pragma unroll
    for (int it = 0; it < 4; it++){
        int idx2 = t + 256*it;
        int k = idx2 >> 5, c = idx2 & 31;
        float w = out_w[c*32 + k];
        shWt2[idx2] = pk2(w, w);
    }
    if (t < 144) shPos2[t] = g_posP2[t];
    if (t >= 224){ int u = t-224; shOB[u] = out_b[u]; }

    // halo load: KV rows (valid) or fp16 kinv/vinv (invalid/OOB)
    for (int u = t; u < NHALO; u += 256){
        int hr = u/HALO_W, hc = u%HALO_W;
        int r = r0 - 1 + hr, c = c0 - 1 + hc;
        int pidx = -1;
        if (r >= 0 && r < H_ && c >= 0 && c < W_) pidx = g_grid[b*HW_ + r*W_ + c];
        u64* dst = shHalo + u*CSTRIDE;
        if (pidx >= 0){
            const u64* src = (const u64*)(g_KVsp + ((size_t)b*HW_ + r*W_ + c)*64);
#pragma unroll
            for (int q = 0; q < 16; q++) dst[q] = src[q];
            shFlag[u] = 1.f;
        } else {
            const u64* src = (const u64*)g_kvinvh;
#pragma unroll
            for (int q = 0; q < 16; q++) dst[q] = src[q];
            shFlag[u] = 0.f;
        }
    }
    __syncthreads();

    // per-cell attention
    int tx = t & 31, ty = t >> 5;
    size_t cellg = (size_t)b*HW_ + (size_t)(r0+ty)*W_ + c0 + tx;
    const float4* qin = (const float4*)(g_Qsp + cellg*32);
    u64 qp[16];
#pragma unroll
    for (int k = 0; k < 8; k++){
        float4 v = qin[k];
        qp[2*k] = pk2(v.x, v.y); qp[2*k+1] = pk2(v.z, v.w);
    }
    const int dr[9] = {0,-1,1,0,-1,1,0,-1,1};
    const int dc[9] = {0,0,0,1,1,1,-1,-1,-1};
    float sum0 = 0.f, sum1 = 0.f;
    u64 ov[16];
#pragma unroll
    for (int k = 0; k < 16; k++) ov[k] = 0ull;

    for (int s = 0; s < 9; s++){
        int nu = (1+ty+dr[s])*HALO_W + 1+tx+dc[s];
        const u64* cb = shHalo + nu*CSTRIDE;
        u64 a0 = 0ull, a1 = 0ull;
#pragma unroll
        for (int k = 0; k < 4; k++){
            unsigned lo, hi; spl(cb[k], lo, hi);
            a0 = ffma2(qp[2*k],   h2f2(lo), a0);
            a0 = ffma2(qp[2*k+1], h2f2(hi), a0);
        }
#pragma unroll
        for (int k = 4; k < 8; k++){
            unsigned lo, hi; spl(cb[k], lo, hi);
            a1 = ffma2(qp[2*k],   h2f2(lo), a1);
            a1 = ffma2(qp[2*k+1], h2f2(hi), a1);
        }
        float w0 = __expf(hsum2(a0));
        float w1 = __expf(hsum2(a1));
        sum0 += w0; sum1 += w1;
        float fl = shFlag[nu];
        u64 Fd = pk2(fl, fl), W0 = pk2(w0, w0), W1 = pk2(w1, w1);
        const u64* pp = shPos2 + s*16;
#pragma unroll
        for (int k = 0; k < 4; k++){
            unsigned lo, hi; spl(cb[8+k], lo, hi);
            u64 t0 = ffma2(Fd, pp[2*k],   h2f2(lo));
            ov[2*k]   = ffma2(W0, t0, ov[2*k]);
            u64 t1 = ffma2(Fd, pp[2*k+1], h2f2(hi));
            ov[2*k+1] = ffma2(W0, t1, ov[2*k+1]);
        }
#pragma unroll
        for (int k = 4; k < 8; k++){
            unsigned lo, hi; spl(cb[8+k], lo, hi);
            u64 t0 = ffma2(Fd, pp[2*k],   h2f2(lo));
            ov[2*k]   = ffma2(W1, t0, ov[2*k]);
            u64 t1 = ffma2(Fd, pp[2*k+1], h2f2(hi));
            ov[2*k+1] = ffma2(W1, t1, ov[2*k+1]);
        }
    }
    {   // normalize
        float rs0 = 1.f/sum0, rs1 = 1.f/sum1;
        u64 R0 = pk2(rs0, rs0), R1 = pk2(rs1, rs1);
#pragma unroll
        for (int k = 0; k < 8; k++){
            ov[k]   = mul2(ov[k],   R0);
            ov[8+k] = mul2(ov[8+k], R1);
        }
    }
    // stage ov into shOs[k][cell]
#pragma unroll
    for (int k = 0; k < 16; k++){
        float2 f = unpk2(ov[k]);
        shOs[(2*k  )*260 + t] = f.x;
        shOs[(2*k+1)*260 + t] = f.y;
    }
    __syncthreads();

    // output projection GEMM -> stage into halo region (reused) [ch][cell] stride 257
    float* oS = (float*)(dsm + SM_HALO);
    {
        int i = t >> 3, j = t & 7;
        u64 acc[4][4];
#pragma unroll
        for (int cc = 0; cc < 4; cc++){
            float bb = shOB[j + 8*cc];
            u64 b2 = pk2(bb, bb);
#pragma unroll
            for (int mm = 0; mm < 4; mm++) acc[cc][mm] = b2;
        }
#pragma unroll 4
        for (int e = 0; e < 32; e++){
            const u64* xr = (const u64*)(shOs + e*260) + i*4;
            ulonglong2 xa = *(const ulonglong2*)(xr);
            ulonglong2 xb = *(const ulonglong2*)(xr + 2);
            u64 xv[4] = {xa.x, xa.y, xb.x, xb.y};
            const u64* wr = shWt2 + e*32 + j;
            u64 av[4];
#pragma unroll
            for (int cc = 0; cc < 4; cc++) av[cc] = wr[8*cc];
#pragma unroll
            for (int cc = 0; cc < 4; cc++)
#pragma unroll
                for (int mm = 0; mm < 4; mm++)
                    acc[cc][mm] = ffma2(av[cc], xv[mm], acc[cc][mm]);
        }
#pragma unroll
        for (int cc = 0; cc < 4; cc++)
#pragma unroll
            for (int mm = 0; mm < 4; mm++){
                int lidx = 8*i + 2*mm;              // even; lidx,lidx+1 same tile row
                int hbase = (1 + (lidx >> 5))*HALO_W + 1 + (lidx & 31);
                float cva = shFlag[hbase], cvb = shFlag[hbase + 1];
                float2 f = unpk2(acc[cc][mm]);
                int ch = j + 8*cc;
                oS[ch*257 + lidx    ] = (cva != 0.f) ? f.x : 0.f;
                oS[ch*257 + lidx + 1] = (cvb != 0.f) ? f.y : 0.f;
            }
    }
    __syncthreads();

    // coalesced channel-major stores: lanes 0..31 cover one 128B row segment
    size_t obase = ((size_t)b*32)*HW_ + (size_t)(r0 + ty)*W_ + c0 + tx;
#pragma unroll
    for (int c = 0; c < 32; c++)
        out[obase + (size_t)c*HW_] = oS[c*257 + t];
}

// ---------------------------------------------------------------
extern "C" void kernel_launch(void* const* d_in, const int* in_sizes, int n_in,
                              void* d_out, int out_size){
    const float* feats = (const float*)d_in[0];
    const int*   coors = (const int*)  d_in[1];
    const float* ln_w  = (const float*)d_in[2];
    const float* ln_b  = (const float*)d_in[3];
    const float* wq    = (const float*)d_in[4];
    const float* bq    = (const float*)d_in[5];
    const float* wk    = (const float*)d_in[6];
    const float* bk    = (const float*)d_in[7];
    const float* wv    = (const float*)d_in[8];
    const float* bv    = (const float*)d_in[9];
    const float* pos_w = (const float*)d_in[10];
    const float* pos_b = (const float*)d_in[11];
    const float* in_w  = (const float*)d_in[12];
    const float* in_b  = (const float*)d_in[13];
    const float* out_w = (const float*)d_in[14];
    const float* out_b = (const float*)d_in[15];

    cudaFuncSetAttribute(k_attn, cudaFuncAttributeMaxDynamicSharedMemorySize, SMEM_ATTN);

    k_setup<<<1 + B_*HW_/256, 256>>>(wq, bq, wk, bk, wv, bv, in_w, in_b, pos_w, pos_b);
    k_qkv<<<NP_/128, 256>>>(feats, ln_w, ln_b, coors);
    k_attn<<<dim3(W_/TW_, H_/TH_, B_), 256, SMEM_ATTN>>>(out_w, out_b, (float*)d_out);
}

// round 14
// speedup vs baseline: 1.2967x; 1.2967x over previous
#include <cuda_runtime.h>
#include <cuda_fp16.h>

#define H_ 512
#define W_ 512
#define C_ 32
#define B_ 2
#define N_ 120000
#define HW_ (H_*W_)
#define NP_ (B_*N_)

typedef unsigned long long u64;

// ---- device scratch (no allocations allowed) ----
__device__ __align__(128) float  g_Q[NP_*C_];
__device__ __align__(128) __half g_KV[NP_*64];       // per-point 128B row: K[32] fp16, V[32] fp16
__device__ __align__(128) float  g_Osp[B_*HW_*C_];   // spatial O (only valid cells written)
__device__ int   g_grid[B_*HW_];
__device__ u64   g_A2p[32*48];    // channel-pair packed: [e][m*16+j] = (A[2j][e],A[2j+1][e])
__device__ u64   g_bf2[48];       // packed bias pairs
__device__ u64   g_posP2[9*16];   // pair-packed posP

// ---- packed f32x2 helpers ----
__device__ __forceinline__ u64 pk2(float lo, float hi){
    u64 r; asm("mov.b64 %0, {%1, %2};" : "=l"(r) : "f"(lo), "f"(hi)); return r;
}
__device__ __forceinline__ float2 unpk2(u64 v){
    float2 f; asm("mov.b64 {%0, %1}, %2;" : "=f"(f.x), "=f"(f.y) : "l"(v)); return f;
}
__device__ __forceinline__ u64 ffma2(u64 a, u64 b, u64 c){
    u64 d; asm("fma.rn.f32x2 %0, %1, %2, %3;" : "=l"(d) : "l"(a), "l"(b), "l"(c)); return d;
}
__device__ __forceinline__ u64 add2(u64 a, u64 b){
    u64 d; asm("add.rn.f32x2 %0, %1, %2;" : "=l"(d) : "l"(a), "l"(b)); return d;
}
__device__ __forceinline__ u64 mul2(u64 a, u64 b){
    u64 d; asm("mul.rn.f32x2 %0, %1, %2;" : "=l"(d) : "l"(a), "l"(b)); return d;
}
__device__ __forceinline__ float hsum2(u64 a){ float2 f = unpk2(a); return f.x + f.y; }
__device__ __forceinline__ u64 h2f2(unsigned v){
    __half2 h = *reinterpret_cast<__half2*>(&v);
    float2 f = __half22float2(h);
    return pk2(f.x, f.y);
}

// ---------------------------------------------------------------
// K0: block 0 = weight fold + pack ENTIRELY FROM SMEM (coalesced
//     one-shot loads; no serial global-latency chains).
//     blocks 1.. = grid clear.
// ---------------------------------------------------------------
__global__ void __launch_bounds__(256) k_setup(
                        const float* __restrict__ wq, const float* __restrict__ bq,
                        const float* __restrict__ wk, const float* __restrict__ bk,
                        const float* __restrict__ wv, const float* __restrict__ bv,
                        const float* __restrict__ in_w, const float* __restrict__ in_b,
                        const float* __restrict__ pos_w, const float* __restrict__ pos_b){
    int t = threadIdx.x;
    if (blockIdx.x > 0){
        g_grid[(blockIdx.x - 1)*256 + t] = -1;   // 2048 blocks * 256 = B_*HW_
        return;
    }
    __shared__ float sW[3*1024];    // wq | wk | wv
    __shared__ float sIW[3*1024];   // in_w
    __shared__ float sA[3*1024];    // folded A
    __shared__ float sB[96];        // bq | bk | bv
    __shared__ float sINB[96];
    __shared__ float sPW[64], sPB[32];
    __shared__ float sBF[96];
    __shared__ float sPP[288];
    for (int i = t; i < 1024; i += 256){
        sW[i] = wq[i]; sW[1024 + i] = wk[i]; sW[2048 + i] = wv[i];
        sIW[i] = in_w[i]; sIW[1024 + i] = in_w[1024 + i]; sIW[2048 + i] = in_w[2048 + i];
    }
    if (t < 32){ sB[t] = bq[t]; sB[32+t] = bk[t]; sB[64+t] = bv[t]; }
    if (t >= 32 && t < 128) sINB[t-32] = in_b[t-32];
    if (t >= 128 && t < 192) sPW[t-128] = pos_w[t-128];
    if (t >= 192 && t < 224) sPB[t-192] = pos_b[t-192];
    __syncthreads();

    // A fold: 3072 items (m,c,e); warp = one (m,c), lanes = e (conflict-free)
    for (int idx = t; idx < 3072; idx += 256){
        int m = idx >> 10, rem = idx & 1023, c = rem >> 5, e = rem & 31;
        const float* iw = sIW + (m*32 + c)*32;
        const float* Wm = sW + m*1024;
        float a = 0.f;
#pragma unroll
        for (int d = 0; d < 32; d++) a += iw[d] * Wm[d*32 + e];
        sA[m*1024 + c*32 + e] = (m==0) ? a*0.25f : a;
    }
    if (t < 96){
        int m = t >> 5, c = t & 31;
        const float* iw = sIW + (m*32 + c)*32;
        float bb = 0.f;
#pragma unroll
        for (int d = 0; d < 32; d++) bb += iw[d] * sB[m*32 + d];
        bb += sINB[t];
        sBF[t] = (m==0) ? bb*0.25f : bb;
    }
    {
        const float drf[9] = {0,-1,1,0,-1,1,0,-1,1};
        const float dcf[9] = {0,0,0,1,1,1,-1,-1,-1};
        for (int idx = t; idx < 288; idx += 256){
            int s = idx >> 5, c = idx & 31;
            const float* iw = sIW + (64 + c)*32;
            float a = 0.f;
#pragma unroll
            for (int d = 0; d < 32; d++){
                float pos = drf[s]*sPW[d*2+0] + dcf[s]*sPW[d*2+1] + sPB[d];
                a += iw[d] * pos;
            }
            sPP[s*32 + c] = a;
        }
    }
    __syncthreads();
    // pack directly to global tables
    for (int idx = t; idx < 1536; idx += 256){
        int e = idx & 31, jj = idx >> 5;      // jj = m*16 + j
        int m = jj >> 4, j = jj & 15;
        g_A2p[e*48 + jj] = pk2(sA[(m*32 + 2*j)*32 + e], sA[(m*32 + 2*j + 1)*32 + e]);
    }
    if (t < 48){
        int m = t >> 4, j = t & 15;
        g_bf2[t] = pk2(sBF[m*32 + 2*j], sBF[m*32 + 2*j + 1]);
    }
    if (t >= 64 && t < 208){
        int u = t - 64;                       // 144 pos pairs
        int s = u >> 4, k = u & 15;
        g_posP2[u] = pk2(sPP[s*32 + 2*k], sPP[s*32 + 2*k + 1]);
    }
}

// ---------------------------------------------------------------
// K1: LN + fused QKV GEMM (channel-pair packed, no transpose) + grid fill.
// ---------------------------------------------------------------
__global__ void __launch_bounds__(256) k_qkv(const float* __restrict__ feats,
                                             const float* __restrict__ ln_w,
                                             const float* __restrict__ ln_b,
                                             const int* __restrict__ coors){
    __shared__ __align__(16) u64   shA2p[32*48];   // 12KB
    __shared__ __align__(16) float Xs[32*128];     // 16KB, [e][p] plain f32
    __shared__ __align__(16) u64   shBp[48];
    int t = threadIdx.x;
    int p0 = blockIdx.x*128;
    if (t >= 128){
        int u = t - 128;
#pragma unroll
        for (int it = 0; it < 12; it++) shA2p[u + 128*it] = g_A2p[u + 128*it];
        if (u < 48) shBp[u] = g_bf2[u];
    } else {
        int p = p0 + t;   // grid sized exactly: 1875*128 == 240000
        {
            int r = __ldg(&coors[2*p]), c = __ldg(&coors[2*p+1]);
            int b = p / N_;
            g_grid[b*HW_ + r*W_ + c] = p - b*N_;
        }
        const float4* xin = (const float4*)(feats + (size_t)p*C_);
        float x[32];
#pragma unroll
        for (int k = 0; k < 8; k++){
            float4 v = xin[k];
            x[4*k] = v.x; x[4*k+1] = v.y; x[4*k+2] = v.z; x[4*k+3] = v.w;
        }
        float mu = 0.f;
#pragma unroll
        for (int e = 0; e < 32; e++) mu += x[e];
        mu *= (1.f/32.f);
        float var = 0.f;
#pragma unroll
        for (int e = 0; e < 32; e++){ float d = x[e]-mu; var += d*d; }
        var *= (1.f/32.f);
        float inv = rsqrtf(var + 1e-5f);
#pragma unroll
        for (int k = 0; k < 32; k++)
            Xs[k*128 + t] = (x[k]-mu)*inv*__ldg(&ln_w[k]) + __ldg(&ln_b[k]);
    }
    __syncthreads();

    int i = t >> 4, j = t & 15;
    u64 acc0[8], acc1[8], acc2[8];
    {
        u64 b0 = shBp[j], b1 = shBp[16 + j], b2 = shBp[32 + j];
#pragma unroll
        for (int p8 = 0; p8 < 8; p8++){ acc0[p8] = b0; acc1[p8] = b1; acc2[p8] = b2; }
    }
#pragma unroll 2
    for (int e = 0; e < 32; e++){
        const float4* xr = (const float4*)(Xs + e*128) + i*2;
        float4 xa = xr[0], xb = xr[1];
        u64 xd[8];
        xd[0] = pk2(xa.x, xa.x); xd[1] = pk2(xa.y, xa.y);
        xd[2] = pk2(xa.z, xa.z); xd[3] = pk2(xa.w, xa.w);
        xd[4] = pk2(xb.x, xb.x); xd[5] = pk2(xb.y, xb.y);
        xd[6] = pk2(xb.z, xb.z); xd[7] = pk2(xb.w, xb.w);
        u64 a0 = shA2p[e*48 + j];
        u64 a1 = shA2p[e*48 + 16 + j];
        u64 a2 = shA2p[e*48 + 32 + j];
#pragma unroll
        for (int p8 = 0; p8 < 8; p8++){
            acc0[p8] = ffma2(a0, xd[p8], acc0[p8]);
            acc1[p8] = ffma2(a1, xd[p8], acc1[p8]);
            acc2[p8] = ffma2(a2, xd[p8], acc2[p8]);
        }
    }
    int prow = p0 + 8*i;
#pragma unroll
    for (int p8 = 0; p8 < 8; p8++)
        *(u64*)(g_Q + (size_t)(prow+p8)*C_ + 2*j) = acc0[p8];
#pragma unroll
    for (int p8 = 0; p8 < 8; p8++){
        float2 fk = unpk2(acc1[p8]);
        float2 fv = unpk2(acc2[p8]);
        __half* row = g_KV + (size_t)(prow+p8)*64;
        *(__half2*)(row + 2*j)      = __floats2half2_rn(fk.x, fk.y);
        *(__half2*)(row + 32 + 2*j) = __floats2half2_rn(fv.x, fv.y);
    }
}

// ---------------------------------------------------------------
// K2: per-point 9-neighbor 2-head attention — single pass, max-free
//     softmax, one 128B KV gather per valid neighbor; output
//     projection GEMM; stores O in SPATIAL layout.
// ---------------------------------------------------------------
__global__ void __launch_bounds__(256) k_attn(const int* __restrict__ coors,
                                              const float* __restrict__ in_b,
                                              const float* __restrict__ out_w,
                                              const float* __restrict__ out_b){
    __shared__ __align__(16) u64   shWt2[32*32];        // [k][c] dup pairs of out_w[c][k], 8KB
    __shared__ __align__(16) float shOs[32*260];        // [k][p] staged ov, 33.3KB
    __shared__ __align__(16) u64   shPos2[9*16];        // pair-packed posP
    __shared__ __align__(16) float shKinv[32];
    __shared__ __align__(16) float shVinv[32];
    __shared__ float shOB[32];
    __shared__ int   shHW[256];                         // per-point flat cell index
    int t = threadIdx.x;
#pragma unroll
    for (int it = 0; it < 4; it++){
        int idx2 = t + 256*it;          // 1024 elems
        int k = idx2 >> 5, c = idx2 & 31;
        float w = out_w[c*32 + k];
        shWt2[idx2] = pk2(w, w);
    }
    if (t < 144) shPos2[t] = g_posP2[t];
    if (t >= 160 && t < 192){ int u = t-160; shKinv[u] = in_b[32+u]; }
    if (t >= 192 && t < 224){ int u = t-192; shVinv[u] = in_b[64+u]; }
    if (t >= 224){ int u = t-224; shOB[u] = out_b[u]; }
    __syncthreads();

    int pbase = blockIdx.x*256;
    int p  = pbase + t;
    int pc = (p < NP_) ? p : (NP_ - 1);
    int b  = pc / N_;

    const float4* qin = (const float4*)(g_Q + (size_t)pc*C_);
    u64 qp[16];
#pragma unroll
    for (int k = 0; k < 8; k++){
        float4 v = qin[k];
        qp[2*k] = pk2(v.x, v.y); qp[2*k+1] = pk2(v.z, v.w);
    }
    int r0 = coors[2*pc], c0 = coors[2*pc+1];
    shHW[t] = b*HW_ + r0*W_ + c0;
    const int* grid = g_grid + b*HW_;
    const int dr[9] = {0,-1,1,0,-1,1,0,-1,1};
    const int dc[9] = {0,0,0,1,1,1,-1,-1,-1};
    int idx[9];
#pragma unroll
    for (int s = 0; s < 9; s++){
        int rr = r0 + dr[s], cc = c0 + dc[s];
        bool ok = (rr >= 0) && (rr < H_) && (cc >= 0) && (cc < W_);
        idx[s] = ok ? grid[rr*W_ + cc] : -1;
    }
    // invalid-slot logit: q . in_b[C:2C]
    const u64* kinvp = (const u64*)shKinv;
    u64 ai0 = 0ull, ai1 = 0ull;
#pragma unroll
    for (int k = 0; k < 8; k++){
        ai0 = ffma2(qp[k],   kinvp[k],   ai0);
        ai1 = ffma2(qp[8+k], kinvp[8+k], ai1);
    }
    float linv0 = hsum2(ai0), linv1 = hsum2(ai1);

    // single pass: unnormalized exp weights, online V accumulate
    float sum0 = 0.f, sum1 = 0.f;
    u64 ov[16];
#pragma unroll
    for (int k = 0; k < 16; k++) ov[k] = 0ull;
    int invcnt = 0;
#pragma unroll
    for (int s = 0; s < 9; s++){
        if (idx[s] >= 0){
            const uint4* kv = (const uint4*)(g_KV + (size_t)(b*N_ + idx[s])*64);
            uint4 k0 = kv[0], k1 = kv[1], k2 = kv[2], k3 = kv[3];
            uint4 v0 = kv[4], v1 = kv[5], v2 = kv[6], v3 = kv[7];
            unsigned kw[16] = {k0.x,k0.y,k0.z,k0.w, k1.x,k1.y,k1.z,k1.w,
                               k2.x,k2.y,k2.z,k2.w, k3.x,k3.y,k3.z,k3.w};
            u64 a0 = 0ull, a1 = 0ull;
#pragma unroll
            for (int k = 0; k < 8; k++) a0 = ffma2(qp[k],   h2f2(kw[k]),   a0);
#pragma unroll
            for (int k = 0; k < 8; k++) a1 = ffma2(qp[8+k], h2f2(kw[8+k]), a1);
            float w0 = __expf(hsum2(a0));
            float w1 = __expf(hsum2(a1));
            sum0 += w0; sum1 += w1;
            unsigned vw[16] = {v0.x,v0.y,v0.z,v0.w, v1.x,v1.y,v1.z,v1.w,
                               v2.x,v2.y,v2.z,v2.w, v3.x,v3.y,v3.z,v3.w};
            u64 W0 = pk2(w0, w0), W1 = pk2(w1, w1);
            const u64* pp = shPos2 + s*16;
#pragma unroll
            for (int k = 0; k < 8; k++)
                ov[k]   = ffma2(W0, add2(h2f2(vw[k]),   pp[k]),   ov[k]);
#pragma unroll
            for (int k = 0; k < 8; k++)
                ov[8+k] = ffma2(W1, add2(h2f2(vw[8+k]), pp[8+k]), ov[8+k]);
        } else invcnt++;
    }
    {   // invalid slots: identical logit, closed-form contribution
        float wi0 = __expf(linv0) * (float)invcnt;
        float wi1 = __expf(linv1) * (float)invcnt;
        sum0 += wi0; sum1 += wi1;
        const u64* vinvp = (const u64*)shVinv;
        u64 W0 = pk2(wi0, wi0), W1 = pk2(wi1, wi1);
#pragma unroll
        for (int k = 0; k < 8; k++){
            ov[k]   = ffma2(W0, vinvp[k],   ov[k]);
            ov[8+k] = ffma2(W1, vinvp[8+k], ov[8+k]);
        }
    }
    {   // normalize
        float rs0 = 1.f/sum0, rs1 = 1.f/sum1;
        u64 R0 = pk2(rs0, rs0), R1 = pk2(rs1, rs1);
#pragma unroll
        for (int k = 0; k < 8; k++){
            ov[k]   = mul2(ov[k],   R0);
            ov[8+k] = mul2(ov[8+k], R1);
        }
    }
    // stage ov[32 floats] into shOs[k][p]
#pragma unroll
    for (int k = 0; k < 16; k++){
        float2 f = unpk2(ov[k]);
        shOs[(2*k  )*260 + t] = f.x;
        shOs[(2*k+1)*260 + t] = f.y;
    }
    __syncthreads();

    // output projection GEMM: thread (i,j): points 8i.. (4 pairs), channels {j+8cc}
    int i = t >> 3, j = t & 7;
    u64 acc[4][4];
#pragma unroll
    for (int cc = 0; cc < 4; cc++){
        float bb = shOB[j + 8*cc];
        u64 b2 = pk2(bb, bb);
#pragma unroll
        for (int mm = 0; mm < 4; mm++) acc[cc][mm] = b2;
    }
#pragma unroll 4
    for (int e = 0; e < 32; e++){
        const u64* xr = (const u64*)(shOs + e*260) + i*4;
        ulonglong2 xa = *(const ulonglong2*)(xr);
        ulonglong2 xb = *(const ulonglong2*)(xr + 2);
        u64 xv[4] = {xa.x, xa.y, xb.x, xb.y};
        const u64* wr = shWt2 + e*32 + j;
        u64 av[4];
#pragma unroll
        for (int cc = 0; cc < 4; cc++) av[cc] = wr[8*cc];
#pragma unroll
        for (int cc = 0; cc < 4; cc++)
#pragma unroll
            for (int mm = 0; mm < 4; mm++)
                acc[cc][mm] = ffma2(av[cc], xv[mm], acc[cc][mm]);
    }
#pragma unroll
    for (int cc = 0; cc < 4; cc++)
#pragma unroll
        for (int mm = 0; mm < 4; mm++){
            int lidx = 8*i + 2*mm;
            int pt = pbase + lidx;
            if (pt < NP_){   // pt even, NP_ even -> pt+1 < NP_ too
                float2 f = unpk2(acc[cc][mm]);
                g_Osp[(size_t)shHW[lidx  ]*C_ + j + 8*cc] = f.x;
                g_Osp[(size_t)shHW[lidx+1]*C_ + j + 8*cc] = f.y;
            }
        }
}

// ---------------------------------------------------------------
// K3: expand to [B,C,H,W] — ordered sparse row reads + smem transpose,
//     coalesced channel-major stores
// ---------------------------------------------------------------
__global__ void __launch_bounds__(256) k_expand(float* __restrict__ out){
    __shared__ float sm[256*33];
    int b   = blockIdx.y;
    int hw0 = blockIdx.x * 256;
    int t   = threadIdx.x;
    int hw  = hw0 + t;
    int idx = g_grid[b*HW_ + hw];
    if (idx >= 0){
        const float4* orow = (const float4*)(g_Osp + ((size_t)b*HW_ + hw)*C_);
#pragma unroll
        for (int k = 0; k < 8; k++){
            float4 v = orow[k];
            sm[t*33 + 4*k + 0] = v.x; sm[t*33 + 4*k + 1] = v.y;
            sm[t*33 + 4*k + 2] = v.z; sm[t*33 + 4*k + 3] = v.w;
        }
    } else {
#pragma unroll
        for (int c = 0; c < 32; c++) sm[t*33 + c] = 0.f;
    }
    __syncthreads();
#pragma unroll
    for (int c = 0; c < 32; c++)
        out[((size_t)(b*C_ + c))*HW_ + hw] = sm[t*33 + c];
}

// ---------------------------------------------------------------
extern "C" void kernel_launch(void* const* d_in, const int* in_sizes, int n_in,
                              void* d_out, int out_size){
    const float* feats = (const float*)d_in[0];
    const int*   coors = (const int*)  d_in[1];
    const float* ln_w  = (const float*)d_in[2];
    const float* ln_b  = (const float*)d_in[3];
    const float* wq    = (const float*)d_in[4];
    const float* bq    = (const float*)d_in[5];
    const float* wk    = (const float*)d_in[6];
    const float* bk    = (const float*)d_in[7];
    const float* wv    = (const float*)d_in[8];
    const float* bv    = (const float*)d_in[9];
    const float* pos_w = (const float*)d_in[10];
    const float* pos_b = (const float*)d_in[11];
    const float* in_w  = (const float*)d_in[12];
    const float* in_b  = (const float*)d_in[13];
    const float* out_w = (const float*)d_in[14];
    const float* out_b = (const float*)d_in[15];

    // block 0: weight fold+pack (smem-staged); blocks 1..2048: grid clear
    k_setup<<<1 + B_*HW_/256, 256>>>(wq, bq, wk, bk, wv, bv, in_w, in_b, pos_w, pos_b);
    k_qkv<<<NP_/128, 256>>>(feats, ln_w, ln_b, coors);
    k_attn<<<(NP_ + 255)/256, 256>>>(coors, in_b, out_w, out_b);
    k_expand<<<dim3(HW_/256, B_), 256>>>((float*)d_out);
}